// round 14
// baseline (speedup 1.0000x reference)
#include <cuda_runtime.h>

#define KDIM 128
#define MAXNNZ 256
#define NTHREADS 512
#define NGRP 8

// Zero-initialized device scratch; the last block resets the counters each
// launch so every graph replay starts clean.
__device__ int          g_nnz;
__device__ unsigned int g_cnt1[NGRP];
__device__ unsigned int g_cnt2;
__device__ int          g_idx[MAXNNZ];
__device__ float        g_val[MAXNNZ];

__device__ __forceinline__ void l2_prefetch(const void* p) {
    asm volatile("prefetch.global.L2 [%0];" :: "l"(p));
}

__device__ __forceinline__ void emit_nnz(
    int idx, float val, int n, int m,
    const float* __restrict__ w_bias,
    const float* __restrict__ uV,
    const float* __restrict__ tV,
    const float* __restrict__ bV)
{
    int slot = atomicAdd(&g_nnz, 1);
    if (slot < MAXNNZ) {
        g_idx[slot] = idx;
        g_val[slot] = val;
    }
    // Warm L2 with this row while the grid converges on the counters.
    const float* base;
    if (idx < n)          base = uV + (size_t)idx * KDIM;
    else if (idx < n + m) base = tV + (size_t)(idx - n) * KDIM;
    else                  base = bV + (size_t)(idx - n - m) * KDIM;
    l2_prefetch(base);
    l2_prefetch(base + 32);
    l2_prefetch(base + 64);
    l2_prefetch(base + 96);
    l2_prefetch(w_bias + idx);
}

__global__ __launch_bounds__(NTHREADS) void fm_loss_kernel(
    const float* __restrict__ x,
    const float* __restrict__ delta,
    const float* __restrict__ w0,
    const float* __restrict__ w_bias,
    const float* __restrict__ uV,
    const float* __restrict__ tV,
    const float* __restrict__ bV,
    float* __restrict__ out,
    int n, int m)
{
    const int p  = n + 2 * m;
    const int p4 = p >> 2;
    const int tid = blockIdx.x * blockDim.x + threadIdx.x;
    const int N   = gridDim.x * blockDim.x;

    // ---- Phase 1: sparse scan of x[:p]; emit (idx, val) + L2 prefetch. ----
    bool wrote = false;
    if (tid < p4) {
        uint4 r = ((const uint4*)x)[tid];
        if (r.x | r.y | r.z | r.w) {   // exact zero-test on float bit patterns
            float vx = __uint_as_float(r.x);
            float vy = __uint_as_float(r.y);
            float vz = __uint_as_float(r.z);
            float vw = __uint_as_float(r.w);
            if (vx != 0.f) emit_nnz(4 * tid + 0, vx, n, m, w_bias, uV, tV, bV);
            if (vy != 0.f) emit_nnz(4 * tid + 1, vy, n, m, w_bias, uV, tV, bV);
            if (vz != 0.f) emit_nnz(4 * tid + 2, vz, n, m, w_bias, uV, tV, bV);
            if (vw != 0.f) emit_nnz(4 * tid + 3, vw, n, m, w_bias, uV, tV, bV);
            wrote = true;
        }
    }
    for (int i = (p4 << 2) + tid; i < p; i += N) {   // tail (p % 4), empty here
        float v = x[i];
        if (v != 0.f) { emit_nnz(i, v, n, m, w_bias, uV, tV, bV); wrote = true; }
    }

    // ---- Phase 2: last-block-done via two-level counter tree. ----
    // Level 1: 8 counters, ~grid/8 concurrent arrivals each (parallel chains).
    // Level 2: 8 arrivals. Total serialized depth ~39 atomics instead of ~245.
    if (wrote) __threadfence();       // release: list writes visible before the
                                      // leader's counter atomic (ordered by bar)
    __syncthreads();
    __shared__ bool s_last;
    if (threadIdx.x == 0) {
        const int G  = gridDim.x;
        const int ng = G < NGRP ? G : NGRP;           // active level-1 groups
        const int g  = blockIdx.x % ng;
        const unsigned quota = (unsigned)((G - 1 - g) / ng + 1); // |{b : b%ng==g}|
        bool last = false;
        if (atomicAdd(&g_cnt1[g], 1u) == quota - 1u) {
            // last block of this group: arrive at level 2
            last = (atomicAdd(&g_cnt2, 1u) == (unsigned)ng - 1u);
        }
        s_last = last;
    }
    __syncthreads();
    if (!s_last) return;
    __threadfence();                  // acquire: see all list writes

    // ---- Phase 3: last block gathers rows and computes everything. ----
    // Three independent scratch loads issued back-to-back (MLP=3).
    const int slot = threadIdx.x < MAXNNZ ? threadIdx.x : MAXNNZ - 1;
    int   nnz_raw = g_nnz;
    int   my_idx  = g_idx[slot];
    float my_val  = g_val[slot];

    const int k   = threadIdx.x & (KDIM - 1);   // dimension 0..127
    const int grp = threadIdx.x >> 7;           // entry-group 0..3

    __shared__ const float* s_ptr[MAXNNZ];
    __shared__ float        s_v[MAXNNZ];
    __shared__ int          s_ty[MAXNNZ];
    __shared__ float        s_bias;
    __shared__ float        s_pu[3][KDIM], s_pt[3][KDIM], s_ps[3][KDIM], s_psq[3][KDIM];
    __shared__ float        s_red[4][5];

    int nnz = nnz_raw < MAXNNZ ? nnz_raw : MAXNNZ;

    if (threadIdx.x == 0) s_bias = 0.f;

    // Resolve row pointer/type from the prefetch; commit only valid slots.
    {
        int idx_c = my_idx < 0 ? 0 : my_idx;            // defensive clamp
        const float* base; int ty;
        if (idx_c < n)          { base = uV + (size_t)idx_c * KDIM;           ty = 0; }
        else if (idx_c < n + m) { base = tV + (size_t)(idx_c - n) * KDIM;     ty = 1; }
        else                    { base = bV + (size_t)(idx_c - n - m) * KDIM; ty = 2; }
        __syncthreads();   // covers s_bias init
        if (threadIdx.x < nnz) {
            s_ptr[threadIdx.x] = base;
            s_v[threadIdx.x]   = my_val;
            s_ty[threadIdx.x]  = ty;
            atomicAdd(&s_bias, my_val * __ldg(&w_bias[idx_c]));
        }
    }
    __syncthreads();

    // Per-dimension accumulation: group g handles entries j ≡ g (mod 4).
    float u = 0.f, t = 0.f, s = 0.f, sq = 0.f;

#define FM_PROC(jj)                                            \
    {                                                          \
        float b   = __ldg(s_ptr[jj] + k);                      \
        float val = s_v[jj];                                   \
        int   ty  = s_ty[jj];                                  \
        float f   = val * b;                                   \
        if (ty == 0)      u  += f;                             \
        else if (ty == 1) t  += f;                             \
        else              { s += f; sq += f * b; }             \
    }

    int j = grp;
    for (; j + 12 < nnz; j += 16) {
        FM_PROC(j); FM_PROC(j + 4); FM_PROC(j + 8); FM_PROC(j + 12);
    }
    for (; j < nnz; j += 4) FM_PROC(j);
#undef FM_PROC

    // Combine the four entry-groups: groups 1-3 publish, group 0 sums.
    if (grp != 0) {
        s_pu[grp - 1][k] = u; s_pt[grp - 1][k] = t;
        s_ps[grp - 1][k] = s; s_psq[grp - 1][k] = sq;
    }
    __syncthreads();

    if (grp == 0) {
        #pragma unroll
        for (int g = 0; g < 3; ++g) {
            u  += s_pu[g][k];
            t  += s_pt[g][k];
            s  += s_ps[g][k];
            sq += s_psq[g][k];
        }
        float ut = u * t, ts = t * s, us = u * s, ss = s * s;
        #pragma unroll
        for (int off = 16; off > 0; off >>= 1) {
            ut += __shfl_down_sync(0xffffffff, ut, off);
            ts += __shfl_down_sync(0xffffffff, ts, off);
            us += __shfl_down_sync(0xffffffff, us, off);
            ss += __shfl_down_sync(0xffffffff, ss, off);
            sq += __shfl_down_sync(0xffffffff, sq, off);
        }
        const int warp = threadIdx.x >> 5;   // 0..3
        const int lane = threadIdx.x & 31;
        if (lane == 0) {
            s_red[warp][0] = ut; s_red[warp][1] = ts; s_red[warp][2] = us;
            s_red[warp][3] = ss; s_red[warp][4] = sq;
        }
    }
    __syncthreads();

    if (threadIdx.x == 0) {
        float UT = 0.f, TS = 0.f, US = 0.f, SS = 0.f, SQ = 0.f;
        #pragma unroll
        for (int w = 0; w < 4; ++w) {
            UT += s_red[w][0]; TS += s_red[w][1]; US += s_red[w][2];
            SS += s_red[w][3]; SQ += s_red[w][4];
        }
        float y = w0[0] + s_bias + UT + TS + 0.5f * (SS - SQ) + US;
        float z = y * delta[0];
        // -log_sigmoid(z) = max(-z, 0) + log1p(exp(-|z|))
        out[0] = fmaxf(-z, 0.f) + log1pf(expf(-fabsf(z)));
        // reset scratch for next graph replay
        g_nnz  = 0;
        g_cnt2 = 0u;
        #pragma unroll
        for (int g = 0; g < NGRP; ++g) g_cnt1[g] = 0u;
    }
}

extern "C" void kernel_launch(void* const* d_in, const int* in_sizes, int n_in,
                              void* d_out, int out_size) {
    const float* x      = (const float*)d_in[0];
    const float* delta  = (const float*)d_in[1];
    // d_in[2] = pmi (unused by the reference)
    const float* w0     = (const float*)d_in[3];
    const float* w_bias = (const float*)d_in[4];
    const float* uV     = (const float*)d_in[5];
    const float* tV     = (const float*)d_in[6];
    const float* bV     = (const float*)d_in[7];
    float* out = (float*)d_out;

    const int n = in_sizes[5] / KDIM;   // u_V is (n, 128)
    const int m = in_sizes[6] / KDIM;   // t_V is (m, 128)
    const int p = n + 2 * m;

    const int threads = NTHREADS;
    const int p4 = p >> 2;
    int blocks = (p4 + threads - 1) / threads;
    if (blocks < 1) blocks = 1;

    fm_loss_kernel<<<blocks, threads>>>(x, delta, w0, w_bias, uV, tV, bV, out, n, m);
}

// round 16
// speedup vs baseline: 1.1805x; 1.1805x over previous
#include <cuda_runtime.h>

#define KDIM 128
#define MAXNNZ 256
#define NTHREADS 512
#define NGROUPS 16   // finish-phase entry groups (one per warp)

// Zero-initialized device scratch; the last block resets the two scalars each
// launch so every graph replay starts clean.
__device__ int          g_nnz;
__device__ unsigned int g_count;
__device__ int          g_idx[MAXNNZ];
__device__ float        g_val[MAXNNZ];

__device__ __forceinline__ void l2_prefetch(const void* p) {
    asm volatile("prefetch.global.L2 [%0];" :: "l"(p));
}

__device__ __forceinline__ void emit_nnz(
    int idx, float val, int n, int m,
    const float* __restrict__ w_bias,
    const float* __restrict__ uV,
    const float* __restrict__ tV,
    const float* __restrict__ bV)
{
    int slot = atomicAdd(&g_nnz, 1);
    if (slot < MAXNNZ) {
        g_idx[slot] = idx;
        g_val[slot] = val;
    }
    // Warm L2 with this row while the grid converges on the counter.
    const float* base;
    if (idx < n)          base = uV + (size_t)idx * KDIM;
    else if (idx < n + m) base = tV + (size_t)(idx - n) * KDIM;
    else                  base = bV + (size_t)(idx - n - m) * KDIM;
    l2_prefetch(base);
    l2_prefetch(base + 32);
    l2_prefetch(base + 64);
    l2_prefetch(base + 96);
    l2_prefetch(w_bias + idx);
}

__global__ __launch_bounds__(NTHREADS) void fm_loss_kernel(
    const float* __restrict__ x,
    const float* __restrict__ delta,
    const float* __restrict__ w0,
    const float* __restrict__ w_bias,
    const float* __restrict__ uV,
    const float* __restrict__ tV,
    const float* __restrict__ bV,
    float* __restrict__ out,
    int n, int m)
{
    const int p  = n + 2 * m;
    const int p4 = p >> 2;
    const int tid = blockIdx.x * blockDim.x + threadIdx.x;
    const int N   = gridDim.x * blockDim.x;

    // ---- Phase 1: sparse scan of x[:p]; emit (idx, val) + L2 prefetch. ----
    bool wrote = false;
    if (tid < p4) {
        uint4 r = ((const uint4*)x)[tid];
        if (r.x | r.y | r.z | r.w) {   // exact zero-test on float bit patterns
            float vx = __uint_as_float(r.x);
            float vy = __uint_as_float(r.y);
            float vz = __uint_as_float(r.z);
            float vw = __uint_as_float(r.w);
            if (vx != 0.f) emit_nnz(4 * tid + 0, vx, n, m, w_bias, uV, tV, bV);
            if (vy != 0.f) emit_nnz(4 * tid + 1, vy, n, m, w_bias, uV, tV, bV);
            if (vz != 0.f) emit_nnz(4 * tid + 2, vz, n, m, w_bias, uV, tV, bV);
            if (vw != 0.f) emit_nnz(4 * tid + 3, vw, n, m, w_bias, uV, tV, bV);
            wrote = true;
        }
    }
    for (int i = (p4 << 2) + tid; i < p; i += N) {   // tail (p % 4), empty here
        float v = x[i];
        if (v != 0.f) { emit_nnz(i, v, n, m, w_bias, uV, tV, bV); wrote = true; }
    }

    // ---- Phase 2: last-block-done (single counter; champion form). ----
    if (wrote) __threadfence();       // release: list writes visible before the
                                      // leader's counter atomic (ordered by bar)
    __syncthreads();
    __shared__ bool s_last;
    if (threadIdx.x == 0)
        s_last = (atomicAdd(&g_count, 1u) == gridDim.x - 1);
    __syncthreads();
    if (!s_last) return;
    __threadfence();                  // acquire: see all list writes

    // ---- Phase 3: last block gathers rows (float4) and computes all. ----
    // Three independent scratch loads issued back-to-back (MLP=3).
    const int slot = threadIdx.x < MAXNNZ ? threadIdx.x : MAXNNZ - 1;
    int   nnz_raw = g_nnz;
    int   my_idx  = g_idx[slot];
    float my_val  = g_val[slot];

    const int lane = threadIdx.x & 31;   // float4-chunk 0..31 (dims 4c..4c+3)
    const int g    = threadIdx.x >> 5;   // entry-group == warp 0..15

    __shared__ const float* s_ptr[MAXNNZ];
    __shared__ float        s_v[MAXNNZ];
    __shared__ int          s_ty[MAXNNZ];
    __shared__ float        s_bias;
    __shared__ float4       s_u[NGROUPS][KDIM / 4];   // float4: natively 16B-aligned
    __shared__ float4       s_t[NGROUPS][KDIM / 4];
    __shared__ float4       s_s[NGROUPS][KDIM / 4];
    __shared__ float        s_sqg[NGROUPS];
    __shared__ float        s_red[4][4];

    int nnz = nnz_raw < MAXNNZ ? nnz_raw : MAXNNZ;

    if (threadIdx.x == 0) s_bias = 0.f;

    // Resolve row pointer/type from the prefetch; commit only valid slots.
    {
        int idx_c = my_idx < 0 ? 0 : my_idx;            // defensive clamp
        const float* base; int ty;
        if (idx_c < n)          { base = uV + (size_t)idx_c * KDIM;           ty = 0; }
        else if (idx_c < n + m) { base = tV + (size_t)(idx_c - n) * KDIM;     ty = 1; }
        else                    { base = bV + (size_t)(idx_c - n - m) * KDIM; ty = 2; }
        __syncthreads();   // covers s_bias init
        if (threadIdx.x < nnz) {
            s_ptr[threadIdx.x] = base;
            s_v[threadIdx.x]   = my_val;
            s_ty[threadIdx.x]  = ty;
            atomicAdd(&s_bias, my_val * __ldg(&w_bias[idx_c]));
        }
    }
    __syncthreads();

    // Gather: group g handles entries j ≡ g (mod 16); each thread loads the
    // float4 chunk `lane` of each row. ~4 independent 16B loads per thread.
    float4 u4 = make_float4(0.f, 0.f, 0.f, 0.f);
    float4 t4 = u4, v4 = u4;
    float  sq = 0.f;

    for (int j = g; j < nnz; j += NGROUPS) {
        float4 b   = __ldg((const float4*)s_ptr[j] + lane);
        float  val = s_v[j];
        int    ty  = s_ty[j];
        if (ty == 0) {
            u4.x += val * b.x; u4.y += val * b.y;
            u4.z += val * b.z; u4.w += val * b.w;
        } else if (ty == 1) {
            t4.x += val * b.x; t4.y += val * b.y;
            t4.z += val * b.z; t4.w += val * b.w;
        } else {
            v4.x += val * b.x; v4.y += val * b.y;
            v4.z += val * b.z; v4.w += val * b.w;
            sq += val * (b.x * b.x + b.y * b.y + b.z * b.z + b.w * b.w);
        }
    }

    // Publish group partials (aligned float4 stores).
    s_u[g][lane] = u4;
    s_t[g][lane] = t4;
    s_s[g][lane] = v4;
    #pragma unroll
    for (int off = 16; off > 0; off >>= 1)
        sq += __shfl_down_sync(0xffffffff, sq, off);
    if (lane == 0) s_sqg[g] = sq;
    __syncthreads();

    // Combine: 128 threads (one per dim k) sum the 16 group partials, then
    // form the four dot products and warp-reduce.
    if (threadIdx.x < KDIM) {
        const int k  = threadIdx.x;
        const int c  = k >> 2;        // float4 chunk
        const int e  = k & 3;         // element within chunk
        float u = 0.f, t = 0.f, s = 0.f;
        #pragma unroll
        for (int gg = 0; gg < NGROUPS; ++gg) {
            const float* pu = (const float*)&s_u[gg][c];
            const float* pt = (const float*)&s_t[gg][c];
            const float* ps = (const float*)&s_s[gg][c];
            u += pu[e];
            t += pt[e];
            s += ps[e];
        }
        float ut = u * t, ts = t * s, us = u * s, ss = s * s;
        #pragma unroll
        for (int off = 16; off > 0; off >>= 1) {
            ut += __shfl_down_sync(0xffffffff, ut, off);
            ts += __shfl_down_sync(0xffffffff, ts, off);
            us += __shfl_down_sync(0xffffffff, us, off);
            ss += __shfl_down_sync(0xffffffff, ss, off);
        }
        const int warp = threadIdx.x >> 5;   // 0..3
        if ((threadIdx.x & 31) == 0) {
            s_red[warp][0] = ut; s_red[warp][1] = ts;
            s_red[warp][2] = us; s_red[warp][3] = ss;
        }
    }
    __syncthreads();

    if (threadIdx.x == 0) {
        float UT = 0.f, TS = 0.f, US = 0.f, SS = 0.f, SQ = 0.f;
        #pragma unroll
        for (int w = 0; w < 4; ++w) {
            UT += s_red[w][0]; TS += s_red[w][1];
            US += s_red[w][2]; SS += s_red[w][3];
        }
        #pragma unroll
        for (int gg = 0; gg < NGROUPS; ++gg) SQ += s_sqg[gg];
        float y = w0[0] + s_bias + UT + TS + 0.5f * (SS - SQ) + US;
        float z = y * delta[0];
        // -log_sigmoid(z) = max(-z, 0) + log1p(exp(-|z|))
        out[0] = fmaxf(-z, 0.f) + log1pf(expf(-fabsf(z)));
        // reset scratch for next graph replay
        g_nnz   = 0;
        g_count = 0u;
    }
}

extern "C" void kernel_launch(void* const* d_in, const int* in_sizes, int n_in,
                              void* d_out, int out_size) {
    const float* x      = (const float*)d_in[0];
    const float* delta  = (const float*)d_in[1];
    // d_in[2] = pmi (unused by the reference)
    const float* w0     = (const float*)d_in[3];
    const float* w_bias = (const float*)d_in[4];
    const float* uV     = (const float*)d_in[5];
    const float* tV     = (const float*)d_in[6];
    const float* bV     = (const float*)d_in[7];
    float* out = (float*)d_out;

    const int n = in_sizes[5] / KDIM;   // u_V is (n, 128)
    const int m = in_sizes[6] / KDIM;   // t_V is (m, 128)
    const int p = n + 2 * m;

    const int threads = NTHREADS;
    const int p4 = p >> 2;
    int blocks = (p4 + threads - 1) / threads;
    if (blocks < 1) blocks = 1;

    fm_loss_kernel<<<blocks, threads>>>(x, delta, w0, w_bias, uV, tV, bV, out, n, m);
}

// round 17
// speedup vs baseline: 1.4018x; 1.1875x over previous
#include <cuda_runtime.h>

#define KDIM 128
#define MAXNNZ 256
#define NTHREADS 512
#define NGROUPS 16   // finish-phase entry groups (one per warp)

// Zero-initialized device scratch; the last block resets the two scalars each
// launch so every graph replay starts clean.
__device__ int          g_nnz;
__device__ unsigned int g_count;
__device__ int          g_idx[MAXNNZ];
__device__ float        g_val[MAXNNZ];

__device__ __forceinline__ void l2_prefetch(const void* p) {
    asm volatile("prefetch.global.L2 [%0];" :: "l"(p));
}

__device__ __forceinline__ void emit_nnz(
    int idx, float val, int n, int m,
    const float* __restrict__ w_bias,
    const float* __restrict__ uV,
    const float* __restrict__ tV,
    const float* __restrict__ bV)
{
    int slot = atomicAdd(&g_nnz, 1);
    if (slot < MAXNNZ) {
        g_idx[slot] = idx;
        g_val[slot] = val;
    }
    // Warm L2 with this row while the grid converges on the counter.
    const float* base;
    if (idx < n)          base = uV + (size_t)idx * KDIM;
    else if (idx < n + m) base = tV + (size_t)(idx - n) * KDIM;
    else                  base = bV + (size_t)(idx - n - m) * KDIM;
    l2_prefetch(base);
    l2_prefetch(base + 32);
    l2_prefetch(base + 64);
    l2_prefetch(base + 96);
    l2_prefetch(w_bias + idx);
}

__device__ __forceinline__ bool scan_vec(
    int i, uint4 r, int n, int m,
    const float* __restrict__ w_bias,
    const float* __restrict__ uV,
    const float* __restrict__ tV,
    const float* __restrict__ bV)
{
    if (!(r.x | r.y | r.z | r.w)) return false;   // exact zero-test on bits
    float vx = __uint_as_float(r.x);
    float vy = __uint_as_float(r.y);
    float vz = __uint_as_float(r.z);
    float vw = __uint_as_float(r.w);
    if (vx != 0.f) emit_nnz(4 * i + 0, vx, n, m, w_bias, uV, tV, bV);
    if (vy != 0.f) emit_nnz(4 * i + 1, vy, n, m, w_bias, uV, tV, bV);
    if (vz != 0.f) emit_nnz(4 * i + 2, vz, n, m, w_bias, uV, tV, bV);
    if (vw != 0.f) emit_nnz(4 * i + 3, vw, n, m, w_bias, uV, tV, bV);
    return true;
}

__global__ __launch_bounds__(NTHREADS) void fm_loss_kernel(
    const float* __restrict__ x,
    const float* __restrict__ delta,
    const float* __restrict__ w0,
    const float* __restrict__ w_bias,
    const float* __restrict__ uV,
    const float* __restrict__ tV,
    const float* __restrict__ bV,
    float* __restrict__ out,
    int n, int m)
{
    const int p  = n + 2 * m;
    const int p4 = p >> 2;
    const int tid = blockIdx.x * blockDim.x + threadIdx.x;
    const int N   = gridDim.x * blockDim.x;

    // ---- Phase 1: one-wave sparse scan of x[:p]; two independent
    // front-batched uint4 loads per thread (MLP=2). ----
    const uint4* x4 = (const uint4*)x;
    const int i0 = tid;
    const int i1 = tid + N;
    uint4 r0 = make_uint4(0u, 0u, 0u, 0u), r1 = r0;
    if (i0 < p4) r0 = x4[i0];
    if (i1 < p4) r1 = x4[i1];

    bool wrote = false;
    wrote |= scan_vec(i0, r0, n, m, w_bias, uV, tV, bV);
    wrote |= scan_vec(i1, r1, n, m, w_bias, uV, tV, bV);

    for (int i = (p4 << 2) + tid; i < p; i += N) {   // tail (p % 4), empty here
        float v = x[i];
        if (v != 0.f) { emit_nnz(i, v, n, m, w_bias, uV, tV, bV); wrote = true; }
    }

    // ---- Phase 2: last-block-done (single counter; champion form). ----
    if (wrote) __threadfence();       // release: list writes visible before the
                                      // leader's counter atomic (ordered by bar)
    __syncthreads();
    __shared__ bool s_last;
    if (threadIdx.x == 0)
        s_last = (atomicAdd(&g_count, 1u) == gridDim.x - 1);
    __syncthreads();
    if (!s_last) return;
    __threadfence();                  // acquire: see all list writes

    // ---- Phase 3: last block gathers rows (float4) and computes all. ----
    // Three independent scratch loads issued back-to-back (MLP=3).
    const int slot = threadIdx.x < MAXNNZ ? threadIdx.x : MAXNNZ - 1;
    int   nnz_raw = g_nnz;
    int   my_idx  = g_idx[slot];
    float my_val  = g_val[slot];

    const int lane = threadIdx.x & 31;   // float4-chunk 0..31 (dims 4c..4c+3)
    const int g    = threadIdx.x >> 5;   // entry-group == warp 0..15

    __shared__ const float* s_ptr[MAXNNZ];
    __shared__ float        s_v[MAXNNZ];
    __shared__ int          s_ty[MAXNNZ];
    __shared__ float        s_bias;
    __shared__ float4       s_u[NGROUPS][KDIM / 4];   // float4: natively 16B-aligned
    __shared__ float4       s_t[NGROUPS][KDIM / 4];
    __shared__ float4       s_s[NGROUPS][KDIM / 4];
    __shared__ float        s_sqg[NGROUPS];
    __shared__ float        s_red[4][4];

    int nnz = nnz_raw < MAXNNZ ? nnz_raw : MAXNNZ;

    if (threadIdx.x == 0) s_bias = 0.f;

    // Resolve row pointer/type from the prefetch; commit only valid slots.
    {
        int idx_c = my_idx < 0 ? 0 : my_idx;            // defensive clamp
        const float* base; int ty;
        if (idx_c < n)          { base = uV + (size_t)idx_c * KDIM;           ty = 0; }
        else if (idx_c < n + m) { base = tV + (size_t)(idx_c - n) * KDIM;     ty = 1; }
        else                    { base = bV + (size_t)(idx_c - n - m) * KDIM; ty = 2; }
        __syncthreads();   // covers s_bias init
        if (threadIdx.x < nnz) {
            s_ptr[threadIdx.x] = base;
            s_v[threadIdx.x]   = my_val;
            s_ty[threadIdx.x]  = ty;
            atomicAdd(&s_bias, my_val * __ldg(&w_bias[idx_c]));
        }
    }
    __syncthreads();

    // Gather: group g handles entries j ≡ g (mod 16); each thread loads the
    // float4 chunk `lane` of each row. ~4 independent 16B loads per thread.
    float4 u4 = make_float4(0.f, 0.f, 0.f, 0.f);
    float4 t4 = u4, v4 = u4;
    float  sq = 0.f;

    for (int j = g; j < nnz; j += NGROUPS) {
        float4 b   = __ldg((const float4*)s_ptr[j] + lane);
        float  val = s_v[j];
        int    ty  = s_ty[j];
        if (ty == 0) {
            u4.x += val * b.x; u4.y += val * b.y;
            u4.z += val * b.z; u4.w += val * b.w;
        } else if (ty == 1) {
            t4.x += val * b.x; t4.y += val * b.y;
            t4.z += val * b.z; t4.w += val * b.w;
        } else {
            v4.x += val * b.x; v4.y += val * b.y;
            v4.z += val * b.z; v4.w += val * b.w;
            sq += val * (b.x * b.x + b.y * b.y + b.z * b.z + b.w * b.w);
        }
    }

    // Publish group partials (aligned float4 stores).
    s_u[g][lane] = u4;
    s_t[g][lane] = t4;
    s_s[g][lane] = v4;
    #pragma unroll
    for (int off = 16; off > 0; off >>= 1)
        sq += __shfl_down_sync(0xffffffff, sq, off);
    if (lane == 0) s_sqg[g] = sq;
    __syncthreads();

    // Combine: 128 threads (one per dim k) sum the 16 group partials, then
    // form the four dot products and warp-reduce.
    if (threadIdx.x < KDIM) {
        const int k  = threadIdx.x;
        const int c  = k >> 2;        // float4 chunk
        const int e  = k & 3;         // element within chunk
        float u = 0.f, t = 0.f, s = 0.f;
        #pragma unroll
        for (int gg = 0; gg < NGROUPS; ++gg) {
            const float* pu = (const float*)&s_u[gg][c];
            const float* pt = (const float*)&s_t[gg][c];
            const float* ps = (const float*)&s_s[gg][c];
            u += pu[e];
            t += pt[e];
            s += ps[e];
        }
        float ut = u * t, ts = t * s, us = u * s, ss = s * s;
        #pragma unroll
        for (int off = 16; off > 0; off >>= 1) {
            ut += __shfl_down_sync(0xffffffff, ut, off);
            ts += __shfl_down_sync(0xffffffff, ts, off);
            us += __shfl_down_sync(0xffffffff, us, off);
            ss += __shfl_down_sync(0xffffffff, ss, off);
        }
        const int warp = threadIdx.x >> 5;   // 0..3
        if ((threadIdx.x & 31) == 0) {
            s_red[warp][0] = ut; s_red[warp][1] = ts;
            s_red[warp][2] = us; s_red[warp][3] = ss;
        }
    }
    __syncthreads();

    if (threadIdx.x == 0) {
        float UT = 0.f, TS = 0.f, US = 0.f, SS = 0.f, SQ = 0.f;
        #pragma unroll
        for (int w = 0; w < 4; ++w) {
            UT += s_red[w][0]; TS += s_red[w][1];
            US += s_red[w][2]; SS += s_red[w][3];
        }
        #pragma unroll
        for (int gg = 0; gg < NGROUPS; ++gg) SQ += s_sqg[gg];
        float y = w0[0] + s_bias + UT + TS + 0.5f * (SS - SQ) + US;
        float z = y * delta[0];
        // -log_sigmoid(z) = max(-z, 0) + log1p(exp(-|z|))
        out[0] = fmaxf(-z, 0.f) + log1pf(expf(-fabsf(z)));
        // reset scratch for next graph replay
        g_nnz   = 0;
        g_count = 0u;
    }
}

extern "C" void kernel_launch(void* const* d_in, const int* in_sizes, int n_in,
                              void* d_out, int out_size) {
    const float* x      = (const float*)d_in[0];
    const float* delta  = (const float*)d_in[1];
    // d_in[2] = pmi (unused by the reference)
    const float* w0     = (const float*)d_in[3];
    const float* w_bias = (const float*)d_in[4];
    const float* uV     = (const float*)d_in[5];
    const float* tV     = (const float*)d_in[6];
    const float* bV     = (const float*)d_in[7];
    float* out = (float*)d_out;

    const int n = in_sizes[5] / KDIM;   // u_V is (n, 128)
    const int m = in_sizes[6] / KDIM;   // t_V is (m, 128)
    const int p = n + 2 * m;

    const int threads = NTHREADS;
    const int p4 = p >> 2;
    const int per_block = threads * 2;           // 2 uint4 per thread (one wave)
    int blocks = (p4 + per_block - 1) / per_block;
    if (blocks < 1) blocks = 1;

    fm_loss_kernel<<<blocks, threads>>>(x, delta, w0, w_bias, uV, tV, bV, out, n, m);
}